// round 11
// baseline (speedup 1.0000x reference)
#include <cuda_runtime.h>

#define HH 96
#define WW 128
#define CC 21
#define NPIX (HH*WW)   // 12288
#define NITER 5

// ---------------- scratch ----------------
__device__ __align__(16) float g_kt[48];       // profile center 24 (blurxpix), 0 beyond r=16
__device__ __align__(16) float g_kt2[64];      // profile center 28 (blury), 0 beyond r=16
__device__ __align__(16) float g_rSx[WW];      // exact full-kernel normalizers
__device__ __align__(16) float g_rSy[HH];
__device__ __align__(16) float g_A[CC*CC];     // compat @ (Ws + Wb)
__device__ __align__(16) float g_ut2[CC*NPIX]; // unaries transposed [c][y*128+x]
__device__ __align__(16) float g_r [CC*NPIX];  // r = A @ softmax(q) [c][y*128+x]
__device__ __align__(16) float g_t1[CC*NPIX];  // after y-blur       [c][y*128+x]

// ======== init: tables + (softmax(u), ut2, r=A@p) ========
// grid 392 x 128: blocks 0..383 pixel work (32 px, x-fastest n); 384..391 tables.
__global__ void init_kernel(const float* __restrict__ un,
                            const float* __restrict__ Ws,
                            const float* __restrict__ Wb,
                            const float* __restrict__ Cm) {
    const float inv18 = 1.0f / 18.0f;
    if (blockIdx.x >= 384) {
        int idx = (blockIdx.x - 384) * 128 + threadIdx.x;
        int total = 48 + 64 + WW + HH + CC*CC;      // 777
        if (idx < total) {
            int i = idx;
            if (i < 48) {
                float d = fabsf((float)(i - 24));
                g_kt[i] = (d <= 16.0f) ? expf(-d * d * inv18) : 0.0f;
            } else if (i < 48 + 64) {
                int j = i - 48;
                float d = fabsf((float)(j - 28));
                g_kt2[j] = (d <= 16.0f) ? expf(-d * d * inv18) : 0.0f;
            } else if (i < 48 + 64 + WW) {
                int x = i - (48 + 64);
                float s = 0.0f;
                for (int xp = 0; xp < WW; xp++) {
                    float d = (float)(x - xp); s += expf(-d * d * inv18);
                }
                g_rSx[x] = 1.0f / s;
            } else if (i < 48 + 64 + WW + HH) {
                int y = i - (48 + 64 + WW);
                float s = 0.0f;
                for (int yp = 0; yp < HH; yp++) {
                    float d = (float)(y - yp); s += expf(-d * d * inv18);
                }
                g_rSy[y] = 1.0f / s;
            } else {
                int a = i - (48 + 64 + WW + HH);
                int rr = a / CC, cc = a % CC;
                float s = 0.0f;
                for (int k = 0; k < CC; k++)
                    s += Cm[rr*CC + k] * (Ws[k*CC + cc] + Wb[k*CC + cc]);
                g_A[a] = s;
            }
        }
        return;
    }
    __shared__ float sA[CC*CC];
    __shared__ float sp[32*21];
    int t = threadIdx.x;
    for (int a = t; a < CC*CC; a += 128) {          // local A (g_A not ready yet)
        int rr = a / CC, cc = a % CC;
        float s = 0.0f;
        for (int k = 0; k < CC; k++)
            s += Cm[rr*CC + k] * (Ws[k*CC + cc] + Wb[k*CC + cc]);
        sA[a] = s;
    }
    __syncthreads();

    int lane = t & 31, w = t >> 5;
    int pxw = lane >> 2, sub = lane & 3;            // 8 px/warp, 4 subs/px
    int px  = w * 8 + pxw;
    int n   = blockIdx.x * 32 + px;                 // n = y*128 + x (x-fastest)
    const float* ub = un + n * CC;                  // NHWC: contiguous per pixel
    int nc    = (sub == 3) ? 6 : 5;
    int cbase = sub * 5;

    float v[6]; float mx = -1e30f;
    #pragma unroll
    for (int k = 0; k < 6; k++)
        if (k < nc) {
            v[k] = ub[cbase + k]; mx = fmaxf(mx, v[k]);
            g_ut2[(cbase + k)*NPIX + n] = v[k];
        }
    mx = fmaxf(mx, __shfl_xor_sync(0xffffffffu, mx, 1));
    mx = fmaxf(mx, __shfl_xor_sync(0xffffffffu, mx, 2));
    float sum = 0.0f;
    #pragma unroll
    for (int k = 0; k < 6; k++)
        if (k < nc) { v[k] = __expf(v[k] - mx); sum += v[k]; }
    sum += __shfl_xor_sync(0xffffffffu, sum, 1);
    sum += __shfl_xor_sync(0xffffffffu, sum, 2);
    float rinv = 1.0f / sum;
    #pragma unroll
    for (int k = 0; k < 6; k++)
        if (k < nc) sp[px*21 + cbase + k] = v[k] * rinv;
    __syncwarp();

    float acc[6] = {0.f,0.f,0.f,0.f,0.f,0.f};
    #pragma unroll
    for (int cp = 0; cp < CC; cp++) {
        float pv = sp[px*21 + cp];
        #pragma unroll
        for (int k = 0; k < 6; k++) acc[k] += sA[(cbase + k)*CC + cp] * pv;
    }
    #pragma unroll
    for (int k = 0; k < 6; k++)
        if (k < nc) g_r[(cbase + k)*NPIX + n] = acc[k];
}

// ======== y-blur (radius 16): t1[c][y][x] = sum_yp r[c][yp][x]*k(|yp-y|) ========
// grid (4,21), block 256 = 32 x-cols x 8 thread-rows; thread computes 12 y outputs.
// All gmem fully coalesced (128B rows); smem stride 129 conflict-free.
__global__ void blury_kernel() {
    __shared__ float skt[64];                       // center-28 table
    __shared__ float sp[32 * 129];                  // [xi][y_in+16], zero-padded
    int tid = threadIdx.x;
    int c  = blockIdx.y;
    int x0 = blockIdx.x * 32;
    if (tid < 64) skt[tid] = g_kt2[tid];
    #pragma unroll
    for (int i = tid; i < 1024; i += 256) {         // zero pads [0,16) & [112,128)
        int col = i >> 5, off = i & 31;
        sp[col*129 + (off < 16 ? off : off + 96)] = 0.0f;
    }
    const float* pc = g_r + c*NPIX + x0;
    #pragma unroll
    for (int i = tid; i < 3072; i += 256) {         // 96 rows x 32 x: 128B coalesced
        int yy = i >> 5, xi = i & 31;
        sp[xi*129 + 16 + yy] = pc[yy*128 + xi];
    }
    __syncthreads();

    int lx = tid & 31, ty = tid >> 5;
    int y0 = ty * 12;
    const float* spv = &sp[lx * 129];
    float acc[12];
    #pragma unroll
    for (int k = 0; k < 12; k++) acc[k] = 0.0f;
    float w[12];
    // tap j: y_in = y0 + j - 16; weight for output k = kprof(|j-16-k|) = skt[12+j-k] ... wait
    // center-28 table: weight = g_kt2[28 + (j-16-k)] = skt[12 + j - k]. j=0: skt[12-k] (>=1).
    #pragma unroll
    for (int k = 0; k < 12; k++) w[k] = skt[12 - k];
    #pragma unroll
    for (int j = 0; j < 44; j++) {                  // taps cover d in [-16,16] for all k
        float v = spv[y0 + j];
        #pragma unroll
        for (int k = 0; k < 12; k++) acc[k] += v * w[k];
        #pragma unroll
        for (int k = 11; k > 0; k--) w[k] = w[k-1];
        w[0] = skt[13 + j];                         // max index 56 < 64
    }
    float* tb = g_t1 + c*NPIX + y0*128 + x0 + lx;
    #pragma unroll
    for (int k = 0; k < 12; k++) tb[k * 128] = acc[k];  // coalesced 128B rows
}

// ======== fused x-blur + update + softmax + A-matvec (or emit) ========
// grid 96 (one y-row each), block 256. smem ~26KB.
__global__ void blurxpix_kernel(float* __restrict__ out, int last) {
    __shared__ float skt[64];
    __shared__ float sA[CC*CC];
    __shared__ float st[CC * 161];                  // [c][xp+16], zero-padded
    __shared__ float sq[128 * CC];                  // q then p, [x][c]
    int tid = threadIdx.x;
    int y = blockIdx.x;
    if (tid < 64) skt[tid] = (tid < 48) ? g_kt[tid] : 0.0f;
    for (int a = tid; a < CC*CC; a += 256) sA[a] = g_A[a];
    for (int i = tid; i < CC*32; i += 256) {        // zero pads [0,16) & [144,160)
        int cc = i >> 5, o = i & 31;
        st[cc*161 + (o < 16 ? o : o + 128)] = 0.0f;
    }
    for (int i = tid; i < CC*32; i += 256) {        // t1 row y, all classes (float4)
        int cc = i >> 5, j = i & 31;
        float4 v = *(const float4*)(g_t1 + cc*NPIX + y*128 + j*4);
        float* d = &st[cc*161 + 16 + j*4];
        d[0] = v.x; d[1] = v.y; d[2] = v.z; d[3] = v.w;
    }
    __syncthreads();

    float rn_y = g_rSy[y];
    // blur: 336 (c, x-tile) tasks, 8 outputs each, sliding weight window
    for (int tile = tid; tile < CC*16; tile += 256) {
        int cc = tile >> 4, xt = tile & 15;
        int x0 = xt * 8;
        const float* stv = &st[cc * 161];
        float acc[8] = {0.f,0.f,0.f,0.f,0.f,0.f,0.f,0.f};
        float w[8];
        #pragma unroll
        for (int k = 0; k < 8; k++) w[k] = skt[8 - k];
        #pragma unroll
        for (int j = 8; j < 48; j++) {              // 40 taps
            float v = stv[x0 + j - 8];
            #pragma unroll
            for (int k = 0; k < 8; k++) acc[k] += v * w[k];
            #pragma unroll
            for (int k = 7; k > 0; k--) w[k] = w[k-1];
            w[0] = skt[j + 1];
        }
        const float* ub = g_ut2 + cc*NPIX + y*128 + x0;
        #pragma unroll
        for (int k = 0; k < 8; k++)
            sq[(x0 + k)*CC + cc] = ub[k] - acc[k] * g_rSx[x0 + k] * rn_y;
    }
    __syncthreads();

    // pixel part: 2 lanes per pixel (lane pair via shfl xor 1)
    int px = tid >> 1, sub = tid & 1;               // px = x
    int nc    = sub ? 10 : 11;
    int cbase = sub ? 11 : 0;
    float* qrow = &sq[px * CC];

    if (last) {                                     // emit out[(x*96+y)*21+c]
        float* ob = out + (px*HH + y)*CC + cbase;
        #pragma unroll
        for (int k = 0; k < 11; k++)
            if (k < nc) ob[k] = qrow[cbase + k];
        return;
    }

    float v[11]; float mx = -1e30f;
    #pragma unroll
    for (int k = 0; k < 11; k++)
        if (k < nc) { v[k] = qrow[cbase + k]; mx = fmaxf(mx, v[k]); }
    mx = fmaxf(mx, __shfl_xor_sync(0xffffffffu, mx, 1));
    float sum = 0.0f;
    #pragma unroll
    for (int k = 0; k < 11; k++)
        if (k < nc) { v[k] = __expf(v[k] - mx); sum += v[k]; }
    sum += __shfl_xor_sync(0xffffffffu, sum, 1);
    float rinv = 1.0f / sum;
    #pragma unroll
    for (int k = 0; k < 11; k++)
        if (k < nc) qrow[cbase + k] = v[k] * rinv;  // overwrite q with p
    __syncwarp();                                   // both subs of px in same warp

    float acc[11];
    #pragma unroll
    for (int k = 0; k < 11; k++) acc[k] = 0.0f;
    #pragma unroll
    for (int cp = 0; cp < CC; cp++) {
        float pv = qrow[cp];
        #pragma unroll
        for (int k = 0; k < 11; k++)
            if (k < nc) acc[k] += sA[(cbase + k)*CC + cp] * pv;
    }
    #pragma unroll
    for (int k = 0; k < 11; k++)
        if (k < nc) g_r[(cbase + k)*NPIX + y*128 + px] = acc[k];
}

extern "C" void kernel_launch(void* const* d_in, const int* in_sizes, int n_in,
                              void* d_out, int out_size) {
    const float* un = (const float*)d_in[0];
    // d_in[1] = rgb: provably unused (bilateral term replaced by spatial in source)
    const float* Ws = (const float*)d_in[2];
    const float* Wb = (const float*)d_in[3];
    const float* Cm = (const float*)d_in[4];
    float* out = (float*)d_out;

    init_kernel<<<392, 128>>>(un, Ws, Wb, Cm);
    for (int it = 0; it < NITER; it++) {
        blury_kernel<<<dim3(4, 21), 256>>>();
        blurxpix_kernel<<<96, 256>>>(out, (it == NITER - 1) ? 1 : 0);
    }
}

// round 12
// speedup vs baseline: 1.3515x; 1.3515x over previous
#include <cuda_runtime.h>

#define HH 96
#define WW 128
#define CC 21
#define NPIX (HH*WW)   // 12288
#define NITER 5
#define NBLK 96

// ---------------- scratch ----------------
__device__ __align__(16) float g_ut2[CC*NPIX]; // unaries transposed [c][y*128+x]
__device__ __align__(16) float g_r [CC*NPIX];  // r = A @ softmax(q) [c][y*128+x]
__device__ __align__(16) float g_t1[CC*NPIX];  // after y-blur       [c][y*128+x]
__device__ unsigned g_cnt = 0;                  // barrier arrivals (returns to 0)
__device__ volatile unsigned g_gen = 0;         // barrier generation (monotonic)

__device__ __forceinline__ void grid_sync() {
    __syncthreads();
    if (threadIdx.x == 0) {
        unsigned gen = g_gen;
        __threadfence();                         // release prior writes
        if (atomicAdd(&g_cnt, 1u) == NBLK - 1u) {
            g_cnt = 0;
            __threadfence();
            g_gen = gen + 1u;
        } else {
            while (g_gen == gen) __nanosleep(32);
        }
        __threadfence();                         // acquire others' writes
    }
    __syncthreads();
}

__global__ void __launch_bounds__(256, 1)
crf_kernel(const float* __restrict__ un,
           const float* __restrict__ Ws,
           const float* __restrict__ Wb,
           const float* __restrict__ Cm,
           float* __restrict__ out) {
    __shared__ float sA[CC*CC];
    __shared__ float s_kt[48];      // profile center 24 (x-blur), 0 beyond r=16
    __shared__ float s_kt2[64];     // profile center 28 (y-blur), 0 beyond r=16
    __shared__ float s_rSx[WW];
    __shared__ float s_rSy[HH];
    __shared__ __align__(16) char s_buf[24288];  // phase-shared scratch

    const int tid = threadIdx.x;
    const int bid = blockIdx.x;
    const float inv18 = 1.0f / 18.0f;

    // ---- block-local tables (no gmem, no cross-block sync needed) ----
    if (tid < 48) {
        float d = fabsf((float)(tid - 24));
        s_kt[tid] = (d <= 16.0f) ? __expf(-d * d * inv18) : 0.0f;
    } else if (tid >= 64 && tid < 128) {
        int j = tid - 64;
        float d = fabsf((float)(j - 28));
        s_kt2[j] = (d <= 16.0f) ? __expf(-d * d * inv18) : 0.0f;
    }
    for (int a = tid; a < CC*CC; a += 256) {
        int rr = a / CC, cc2 = a % CC;
        float s = 0.0f;
        for (int k = 0; k < CC; k++)
            s += Cm[rr*CC + k] * (Ws[k*CC + cc2] + Wb[k*CC + cc2]);
        sA[a] = s;
    }
    __syncthreads();
    if (tid < WW) {                               // normalizers from truncated profile
        float s = 0.0f;
        #pragma unroll
        for (int d = -16; d <= 16; d++) {
            int xp = tid + d;
            if (0 <= xp && xp < WW) s += s_kt[24 + d];
        }
        s_rSx[tid] = 1.0f / s;
    } else if (tid < WW + HH) {
        int y = tid - WW;
        float s = 0.0f;
        #pragma unroll
        for (int d = -16; d <= 16; d++) {
            int yp = y + d;
            if (0 <= yp && yp < HH) s += s_kt2[28 + d];
        }
        s_rSy[y] = 1.0f / s;
    }
    __syncthreads();

    // ---- phase 0: softmax(u), store ut2 + r = A@p (128 px/block, 2 passes) ----
    {
        float* sp0 = (float*)s_buf;               // [64][21], rows warp-private
        int lane = tid & 31, w = tid >> 5;
        int pxw = lane >> 2, sub = lane & 3;
        int nc    = (sub == 3) ? 6 : 5;
        int cbase = sub * 5;
        for (int pass = 0; pass < 2; pass++) {
            int px = w * 8 + pxw;                 // 0..63
            int n  = bid * 128 + pass * 64 + px;  // n = y*128 + x
            const float* ub = un + n * CC;
            float v[6]; float mx = -1e30f;
            #pragma unroll
            for (int k = 0; k < 6; k++)
                if (k < nc) {
                    v[k] = ub[cbase + k]; mx = fmaxf(mx, v[k]);
                    g_ut2[(cbase + k)*NPIX + n] = v[k];
                }
            mx = fmaxf(mx, __shfl_xor_sync(0xffffffffu, mx, 1));
            mx = fmaxf(mx, __shfl_xor_sync(0xffffffffu, mx, 2));
            float sum = 0.0f;
            #pragma unroll
            for (int k = 0; k < 6; k++)
                if (k < nc) { v[k] = __expf(v[k] - mx); sum += v[k]; }
            sum += __shfl_xor_sync(0xffffffffu, sum, 1);
            sum += __shfl_xor_sync(0xffffffffu, sum, 2);
            float rinv = 1.0f / sum;
            #pragma unroll
            for (int k = 0; k < 6; k++)
                if (k < nc) sp0[px*21 + cbase + k] = v[k] * rinv;
            __syncwarp();                         // row px touched by this warp only

            float acc[6] = {0.f,0.f,0.f,0.f,0.f,0.f};
            #pragma unroll
            for (int cp = 0; cp < CC; cp++) {
                float pv = sp0[px*21 + cp];
                #pragma unroll
                for (int k = 0; k < 6; k++) acc[k] += sA[(cbase + k)*CC + cp] * pv;
            }
            #pragma unroll
            for (int k = 0; k < 6; k++)
                if (k < nc) g_r[(cbase + k)*NPIX + n] = acc[k];
            __syncwarp();
        }
    }
    grid_sync();

    // ---- mean-field iterations ----
    for (int it = 0; it < NITER; it++) {
        // ===== y-blur phase: 84 tasks (c x 4 strips of 32 x) =====
        if (bid < 84) {
            float* sp = (float*)s_buf;            // [128][33]: row = y+16, zero-padded
            int c  = bid >> 2;
            int x0 = (bid & 3) * 32;
            for (int i = tid; i < 1024; i += 256) {       // pads: rows 0..15, 112..127
                int rr = i >> 5, xi = i & 31;
                sp[((rr < 16) ? rr : rr + 96)*33 + xi] = 0.0f;
            }
            const float* pc = g_r + c*NPIX + x0;
            #pragma unroll
            for (int i = tid; i < 3072; i += 256) {       // 96 rows x 32: 128B coalesced
                int yy = i >> 5, xi = i & 31;
                sp[(yy + 16)*33 + xi] = pc[yy*128 + xi];
            }
            __syncthreads();

            int x = tid & 31, yg = tid >> 5;
            int y0 = yg * 12;
            float wv[33];
            #pragma unroll
            for (int j = 0; j < 33; j++) wv[j] = s_kt2[12 + j];   // kprof(|j-16|)
            float* tb = g_t1 + c*NPIX + y0*128 + x0 + x;
            #pragma unroll
            for (int k = 0; k < 12; k++) {
                const float* col = sp + (y0 + k)*33 + x;
                float a0 = 0.f, a1 = 0.f, a2 = 0.f;
                #pragma unroll
                for (int j = 0; j < 33; j += 3) {
                    a0 += col[j*33] * wv[j];
                    if (j + 1 < 33) a1 += col[(j+1)*33] * wv[j+1];
                    if (j + 2 < 33) a2 += col[(j+2)*33] * wv[j+2];
                }
                tb[k*128] = a0 + a1 + a2;                 // coalesced
            }
        }
        grid_sync();

        // ===== fused x-blur + update + softmax + matvec (or emit), y = bid =====
        {
            float* st = (float*)s_buf;                    // [21][161], zero-padded
            float* sq = (float*)(s_buf + CC*161*4);       // [128][21]
            int y = bid;
            for (int i = tid; i < CC*32; i += 256) {      // pads [0,16) & [144,160)
                int cc = i >> 5, o = i & 31;
                st[cc*161 + (o < 16 ? o : o + 128)] = 0.0f;
            }
            for (int i = tid; i < CC*32; i += 256) {      // t1 row y, float4
                int cc = i >> 5, j = i & 31;
                float4 v = *(const float4*)(g_t1 + cc*NPIX + y*128 + j*4);
                float* d = &st[cc*161 + 16 + j*4];
                d[0] = v.x; d[1] = v.y; d[2] = v.z; d[3] = v.w;
            }
            __syncthreads();

            float rn_y = s_rSy[y];
            for (int tile = tid; tile < CC*16; tile += 256) {
                int cc = tile >> 4, xt = tile & 15;
                int x0 = xt * 8;
                const float* stv = &st[cc * 161];
                float acc[8] = {0.f,0.f,0.f,0.f,0.f,0.f,0.f,0.f};
                float w[8];
                #pragma unroll
                for (int k = 0; k < 8; k++) w[k] = s_kt[8 - k];
                #pragma unroll
                for (int j = 8; j < 48; j++) {            // 40 taps
                    float v = stv[x0 + j - 8];
                    #pragma unroll
                    for (int k = 0; k < 8; k++) acc[k] += v * w[k];
                    #pragma unroll
                    for (int k = 7; k > 0; k--) w[k] = w[k-1];
                    w[0] = s_kt[j + 1];
                }
                const float* ub = g_ut2 + cc*NPIX + y*128 + x0;
                #pragma unroll
                for (int k = 0; k < 8; k++)
                    sq[(x0 + k)*CC + cc] = ub[k] - acc[k] * s_rSx[x0 + k] * rn_y;
            }
            __syncthreads();

            int px = tid >> 1, sub = tid & 1;             // 2 lanes per pixel
            int nc    = sub ? 10 : 11;
            int cbase = sub ? 11 : 0;
            float* qrow = &sq[px * CC];

            if (it == NITER - 1) {                        // emit out[(x*96+y)*21+c]
                float* ob = out + (px*HH + y)*CC + cbase;
                #pragma unroll
                for (int k = 0; k < 11; k++)
                    if (k < nc) ob[k] = qrow[cbase + k];
            } else {
                float v[11]; float mx = -1e30f;
                #pragma unroll
                for (int k = 0; k < 11; k++)
                    if (k < nc) { v[k] = qrow[cbase + k]; mx = fmaxf(mx, v[k]); }
                mx = fmaxf(mx, __shfl_xor_sync(0xffffffffu, mx, 1));
                float sum = 0.0f;
                #pragma unroll
                for (int k = 0; k < 11; k++)
                    if (k < nc) { v[k] = __expf(v[k] - mx); sum += v[k]; }
                sum += __shfl_xor_sync(0xffffffffu, sum, 1);
                float rinv = 1.0f / sum;
                #pragma unroll
                for (int k = 0; k < 11; k++)
                    if (k < nc) qrow[cbase + k] = v[k] * rinv;   // q -> p
                __syncwarp();

                float acc[11];
                #pragma unroll
                for (int k = 0; k < 11; k++) acc[k] = 0.0f;
                #pragma unroll
                for (int cp = 0; cp < CC; cp++) {
                    float pv = qrow[cp];
                    #pragma unroll
                    for (int k = 0; k < 11; k++)
                        if (k < nc) acc[k] += sA[(cbase + k)*CC + cp] * pv;
                }
                #pragma unroll
                for (int k = 0; k < 11; k++)
                    if (k < nc) g_r[(cbase + k)*NPIX + y*128 + px] = acc[k];
            }
        }
        if (it < NITER - 1) grid_sync();
    }
}

extern "C" void kernel_launch(void* const* d_in, const int* in_sizes, int n_in,
                              void* d_out, int out_size) {
    const float* un = (const float*)d_in[0];
    // d_in[1] = rgb: provably unused (bilateral term replaced by spatial in source)
    const float* Ws = (const float*)d_in[2];
    const float* Wb = (const float*)d_in[3];
    const float* Cm = (const float*)d_in[4];
    float* out = (float*)d_out;

    crf_kernel<<<NBLK, 256>>>(un, Ws, Wb, Cm, out);
}